// round 15
// baseline (speedup 1.0000x reference)
#include <cuda_runtime.h>
#include <cuda_bf16.h>
#include <cuda_fp16.h>
#include <cstdint>
#include <math.h>

#define N_RES_MAX 30000
#define N_ATOMS   6
#define HID       128
#define N_CHUNKS  11

// ---- scratch (device globals; no allocations allowed) ----
__device__ float         g_Q[N_RES_MAX * 9];
__device__ unsigned char g_valid[N_RES_MAX];
__device__ unsigned char g_Bimg[N_CHUNKS * 16384];       // pre-swizzled W chunks (fp16, 16KB each)

// =====================================================================
// helpers
// =====================================================================
__device__ __forceinline__ uint32_t smem_to_u32(const void* p) {
    uint32_t a;
    asm("{ .reg .u64 t; cvta.to.shared.u64 t, %1; cvt.u32.u64 %0, t; }" : "=r"(a) : "l"(p));
    return a;
}
__device__ __forceinline__ uint32_t swz(uint32_t off) { return off ^ ((off >> 3) & 0x70); }
__device__ __forceinline__ uint32_t packh2(float a, float b) {
    __half2 h = __floats2half2_rn(a, b);
    return *(uint32_t*)&h;
}
__device__ __forceinline__ float sgnf(float x) {
    return (x > 0.f) ? 1.f : ((x < 0.f) ? -1.f : 0.f);
}
__device__ __forceinline__ void norm3(float& x, float& y, float& z) {
    float n = sqrtf(x * x + y * y + z * z);
    float inv = 1.f / fmaxf(n, 1e-12f);
    x *= inv; y *= inv; z *= inv;
}
__device__ __forceinline__ void ldm_x4(uint32_t* r, uint32_t addr) {
    asm volatile("ldmatrix.sync.aligned.m8n8.x4.shared.b16 {%0,%1,%2,%3}, [%4];"
        : "=r"(r[0]), "=r"(r[1]), "=r"(r[2]), "=r"(r[3]) : "r"(addr));
}
__device__ __forceinline__ void mma_fp16(float* c, const uint32_t* a, const uint32_t* b) {
    asm volatile("mma.sync.aligned.m16n8k16.row.col.f32.f16.f16.f32 "
        "{%0,%1,%2,%3}, {%4,%5,%6,%7}, {%8,%9}, {%0,%1,%2,%3};"
        : "+f"(c[0]), "+f"(c[1]), "+f"(c[2]), "+f"(c[3])
        : "r"(a[0]), "r"(a[1]), "r"(a[2]), "r"(a[3]), "r"(b[0]), "r"(b[1]));
}
__device__ __forceinline__ void cp_async16(uint32_t smem_dst, const void* gsrc) {
    asm volatile("cp.async.cg.shared.global [%0], [%1], 16;"
        :: "r"(smem_dst), "l"(gsrc) : "memory");
}
__device__ __forceinline__ void cp_async_commit() {
    asm volatile("cp.async.commit_group;" ::: "memory");
}
__device__ __forceinline__ void cp_async_wait0() {
    asm volatile("cp.async.wait_group 0;" ::: "memory");
}

// set half #idx inside packed uint array (idx must be compile-time under unroll)
#define SET_HALF(arr, idx, f) do {                                        \
    uint32_t hv = (uint32_t)__half_as_ushort(__float2half(f));            \
    if ((idx) & 1) (arr)[(idx) >> 1] |= (hv << 16);                       \
    else           (arr)[(idx) >> 1] |= hv;                               \
} while (0)

// =====================================================================
// Kernel 1 (FUSED node): per-residue features (44) + Q frames + validity,
// then warp-per-residue matvec (44->128) + bias + layernorm.
// 128 threads/block = 128 residues; feats staged in smem.
// =====================================================================
__global__ void __launch_bounds__(128)
node_fused_kernel(const float* __restrict__ coords,
                  const float* __restrict__ cX,
                  const int*   __restrict__ batch,
                  const float* __restrict__ W,
                  const float* __restrict__ b,
                  const float* __restrict__ lnw,
                  const float* __restrict__ lnb,
                  float* __restrict__ out,
                  int n_res)
{
    __shared__ float s_feat[128][45];
    const int tid = threadIdx.x;
    const int r0  = blockIdx.x * 128;
    int r = r0 + tid;
    const int L = n_res * N_ATOMS;

    if (r < n_res) {
        bool bnd  = (r > 0)         && (batch[r]     != batch[r - 1]);
        bool bndn = (r < n_res - 1) && (batch[r + 1] != batch[r]);

        float xp[9][3];
        #pragma unroll
        for (int i = 0; i < 9; i++) {
            int j = 6 * r + i - 1;
            j = max(0, min(L - 1, j));
            xp[i][0] = coords[j * 3 + 0];
            xp[i][1] = coords[j * 3 + 1];
            xp[i][2] = coords[j * 3 + 2];
        }
        float U[8][3];
        #pragma unroll
        for (int i = 0; i < 8; i++) {
            float dx = xp[i + 1][0] - xp[i][0];
            float dy = xp[i + 1][1] - xp[i][1];
            float dz = xp[i + 1][2] - xp[i][2];
            norm3(dx, dy, dz);
            U[i][0] = dx; U[i][1] = dy; U[i][2] = dz;
        }

        float feat[44];
        #pragma unroll
        for (int a = 0; a < 6; a++) {
            int j = 6 * r + a;
            bool dm = (j >= 1) && (j <= L - 3) && !(bnd && a == 0) && !(bndn && a >= 4);
            float sv = 0.f, cv = 0.f;
            if (dm) {
                float c1x = U[a][1] * U[a + 1][2] - U[a][2] * U[a + 1][1];
                float c1y = U[a][2] * U[a + 1][0] - U[a][0] * U[a + 1][2];
                float c1z = U[a][0] * U[a + 1][1] - U[a][1] * U[a + 1][0];
                norm3(c1x, c1y, c1z);
                float c2x = U[a + 1][1] * U[a + 2][2] - U[a + 1][2] * U[a + 2][1];
                float c2y = U[a + 1][2] * U[a + 2][0] - U[a + 1][0] * U[a + 2][2];
                float c2z = U[a + 1][0] * U[a + 2][1] - U[a + 1][1] * U[a + 2][0];
                norm3(c2x, c2y, c2z);
                float d = c1x * c2x + c1y * c2y + c1z * c2z;
                d = fminf(fmaxf(d, -1.f + 1e-6f), 1.f - 1e-6f);
                float sg = sgnf(c2x * U[a][0] + c2y * U[a][1] + c2z * U[a][2]);
                float dih = acosf(d) * sg;
                sv = sinf(dih); cv = cosf(dih);
            }
            feat[2 * a]     = sv;
            feat[2 * a + 1] = cv;
            bool am = (j >= 1) && (j <= L - 2) && !(bnd && a == 0) && !(bndn && a == 5);
            float sa = 0.f, ca = 0.f;
            if (am) {
                float ax = xp[a][0] - xp[a + 1][0];
                float ay = xp[a][1] - xp[a + 1][1];
                float az = xp[a][2] - xp[a + 1][2];
                norm3(ax, ay, az);
                float bx = xp[a + 2][0] - xp[a + 1][0];
                float by = xp[a + 2][1] - xp[a + 1][1];
                float bz = xp[a + 2][2] - xp[a + 1][2];
                norm3(bx, by, bz);
                ca = ax * bx + ay * by + az * bz;
                sa = sqrtf(1.f - ca * ca + 1e-6f);
            }
            feat[12 + 2 * a] = sa;
            feat[13 + 2 * a] = ca;
        }

        float Q[3][3] = {{0.f,0.f,0.f},{0.f,0.f,0.f},{0.f,0.f,0.f}};
        bool qv = false;
        float cx0[3] = { cX[r * 3 + 0], cX[r * 3 + 1], cX[r * 3 + 2] };
        if (r >= 1 && r <= n_res - 2) {
            float cm[3] = { cX[(r - 1) * 3 + 0], cX[(r - 1) * 3 + 1], cX[(r - 1) * 3 + 2] };
            float cp[3] = { cX[(r + 1) * 3 + 0], cX[(r + 1) * 3 + 1], cX[(r + 1) * 3 + 2] };
            float u0x = cx0[0] - cm[0], u0y = cx0[1] - cm[1], u0z = cx0[2] - cm[2];
            norm3(u0x, u0y, u0z);
            float u1x = cp[0] - cx0[0], u1y = cp[1] - cx0[1], u1z = cp[2] - cx0[2];
            norm3(u1x, u1y, u1z);
            float bx = u0x - u1x, by = u0y - u1y, bz = u0z - u1z;
            norm3(bx, by, bz);
            float nx = u0y * u1z - u0z * u1y;
            float ny = u0z * u1x - u0x * u1z;
            float nz = u0x * u1y - u0y * u1x;
            norm3(nx, ny, nz);
            float ccx = by * nz - bz * ny;
            float ccy = bz * nx - bx * nz;
            float ccz = bx * ny - by * nx;
            qv = !bnd && !bndn;
            float m = qv ? 1.f : 0.f;
            Q[0][0] = bx * m; Q[0][1] = nx * m; Q[0][2] = ccx * m;
            Q[1][0] = by * m; Q[1][1] = ny * m; Q[1][2] = ccy * m;
            Q[2][0] = bz * m; Q[2][1] = nz * m; Q[2][2] = ccz * m;
        }
        g_valid[r] = qv ? 1 : 0;
        #pragma unroll
        for (int k = 0; k < 3; k++)
            #pragma unroll
            for (int j = 0; j < 3; j++)
                g_Q[r * 9 + k * 3 + j] = Q[k][j];

        const int keep[5] = {0, 2, 3, 4, 5};
        #pragma unroll
        for (int ai = 0; ai < 5; ai++) {
            int a = keep[ai];
            float dx = xp[a + 1][0] - cx0[0];
            float dy = xp[a + 1][1] - cx0[1];
            float dz = xp[a + 1][2] - cx0[2];
            float ss = dx * dx + dy * dy + dz * dz;
            feat[24 + ai] = 0.5f * logf(ss + 1e-6f);
            float inv = 1.f / fmaxf(sqrtf(ss), 1e-12f);
            float nx = dx * inv, ny = dy * inv, nz = dz * inv;
            #pragma unroll
            for (int i = 0; i < 3; i++)
                feat[29 + ai * 3 + i] = Q[0][i] * nx + Q[1][i] * ny + Q[2][i] * nz;
        }
        #pragma unroll
        for (int k = 0; k < 44; k++)
            s_feat[tid][k] = feat[k];
    }
    __syncthreads();

    // phase 2: warp-per-residue matvec + layernorm
    const int wid = tid >> 5, lane = tid & 31;
    for (int ri = wid; ri < 128; ri += 4) {
        int rr = r0 + ri;
        if (rr >= n_res) break;
        const float* f = s_feat[ri];
        float acc[4];
        #pragma unroll
        for (int u = 0; u < 4; u++) acc[u] = b[lane + 32 * u];
        #pragma unroll 4
        for (int k = 0; k < 44; k++) {
            float fv = f[k];
            #pragma unroll
            for (int u = 0; u < 4; u++)
                acc[u] += fv * W[k * HID + lane + 32 * u];
        }
        float s1 = acc[0] + acc[1] + acc[2] + acc[3];
        float s2 = acc[0]*acc[0] + acc[1]*acc[1] + acc[2]*acc[2] + acc[3]*acc[3];
        #pragma unroll
        for (int o = 16; o > 0; o >>= 1) {
            s1 += __shfl_xor_sync(0xffffffffu, s1, o);
            s2 += __shfl_xor_sync(0xffffffffu, s2, o);
        }
        float mu  = s1 * (1.f / 128.f);
        float var = s2 * (1.f / 128.f) - mu * mu;
        float rs  = rsqrtf(var + 1e-5f);
        #pragma unroll
        for (int u = 0; u < 4; u++) {
            int c = lane + 32 * u;
            out[(size_t)rr * HID + c] = (acc[u] - mu) * rs * lnw[c] + lnb[c];
        }
    }
}

// =====================================================================
// Kernel 2: W prep — pre-swizzled SW128 fp16 image per 64-K chunk (16KB)
// Plane order: k 0..575 rbf (feature 4+k);  k 576..703: col = k-576:
//   col 0..53   -> dir feature 580+col        (half0 planes)
//   col 54..55  -> pad (0)
//   col 56..109 -> dir feature 634+(col-56)   (half1 planes)
//   col 110..113-> quat feature col-110
//   col 114..127-> pad (0)
// =====================================================================
__device__ __forceinline__ int feat_of_k(int k) {
    if (k < 576) return 4 + k;
    int col = k - 576;
    if (col < 54)  return 580 + col;
    if (col < 56)  return -1;
    if (col < 110) return 634 + (col - 56);
    if (col < 114) return col - 110;
    return -1;
}

__global__ void bprep_kernel(const float* __restrict__ eW)
{
    int c = blockIdx.x;
    char* img = (char*)(g_Bimg + (size_t)c * 16384);
    for (int i = threadIdx.x; i < 4096; i += blockDim.x) {
        int n = i >> 5, kp = i & 31;            // kp = pair of k
        int k0 = c * 64 + kp * 2;
        int fa = feat_of_k(k0), fb = feat_of_k(k0 + 1);
        float w0 = (fa >= 0) ? eW[fa * HID + n] : 0.f;
        float w1 = (fb >= 0) ? eW[fb * HID + n] : 0.f;
        *(uint32_t*)(img + swz((uint32_t)(n * 128 + kp * 4))) = packh2(w0, w1);
    }
}

// =====================================================================
// Kernel 3 (FUSED edge): features + GEMM + bias + layernorm.
// M=128 edges/CTA, N=128, K=704 in 11 chunks, order [9,10,0..8];
// chunks 9/10 staged directly into the A double-buffer. 2 CTAs/SM.
// smem: A[2]@0,16384 | B[2]@32768,49152 | D(36 planes f32)@65536 |
//       red(2KB)@83968.   total 86016 B
// =====================================================================
#define SB_OFF   32768
#define SD_OFF   65536
#define RED_OFF  83968
#define SMEM_TOT 86016

__device__ __forceinline__ void produce_B_async(uint32_t sb, int b, int c, int tid)
{
    const char* src = (const char*)(g_Bimg + (size_t)c * 16384);
    uint32_t dst = sb + SB_OFF + b * 16384;
    #pragma unroll
    for (int i = 0; i < 4; i++)
        cp_async16(dst + (tid + i * 256) * 16, src + (tid + i * 256) * 16);
    cp_async_commit();
}

// ---- per-tile staging: 2 threads/edge; dirs+quat go straight into the
//      swizzled A buffers (slot0 = chunk 9, slot1 = chunk 10) ----
__device__ __forceinline__ void stage_tile(char* smem,
                                           const float* __restrict__ coords,
                                           const int*   __restrict__ eidx,
                                           int n_edges, int e0, int tid)
{
    float* s_D = (float*)(smem + SD_OFF);
    int e = tid >> 1, half = tid & 1;
    int ge = min(e0 + e, n_edges - 1);
    int s = eidx[ge], t = eidx[n_edges + ge];

    float Qt[9];
    #pragma unroll
    for (int i = 0; i < 9; i++) Qt[i] = g_Q[t * 9 + i];
    float ct[9];
    #pragma unroll
    for (int j = 0; j < 9; j++) ct[j] = coords[t * 18 + half * 9 + j];
    float cs[18];
    #pragma unroll
    for (int j = 0; j < 18; j++) cs[j] = coords[s * 18 + j];

    uint32_t hb[32];
    #pragma unroll
    for (int j = 0; j < 32; j++) hb[j] = 0;

    #pragma unroll
    for (int pp = 0; pp < 18; pp++) {
        int tl = pp / 6, sa = pp % 6;
        int p  = half * 18 + pp;                 // global pair index ta*6+sa
        float dx = cs[sa * 3 + 0] - ct[tl * 3 + 0];
        float dy = cs[sa * 3 + 1] - ct[tl * 3 + 1];
        float dz = cs[sa * 3 + 2] - ct[tl * 3 + 2];
        float ss2 = dx * dx + dy * dy + dz * dz;
        s_D[p * 128 + e] = sqrtf(ss2 + 1e-6f);
        float inv = 1.f / fmaxf(sqrtf(ss2), 1e-12f);
        float nx = dx * inv, ny = dy * inv, nz = dz * inv;
        float v0 = Qt[0] * nx + Qt[3] * ny + Qt[6] * nz;
        float v1 = Qt[1] * nx + Qt[4] * ny + Qt[7] * nz;
        float v2 = Qt[2] * nx + Qt[5] * ny + Qt[8] * nz;
        SET_HALF(hb, pp * 3 + 0, v0);
        SET_HALF(hb, pp * 3 + 1, v1);
        SET_HALF(hb, pp * 3 + 2, v2);
    }

    if (half) {
        // quaternion appended at local positions 54..57
        float Qs[9];
        #pragma unroll
        for (int i = 0; i < 9; i++) Qs[i] = g_Q[s * 9 + i];
        float m = (g_valid[s] && g_valid[t]) ? 1.f : 0.f;
        float R[3][3];
        #pragma unroll
        for (int i = 0; i < 3; i++)
            #pragma unroll
            for (int j = 0; j < 3; j++)
                R[i][j] = Qt[0 * 3 + i] * Qs[0 * 3 + j]
                        + Qt[1 * 3 + i] * Qs[1 * 3 + j]
                        + Qt[2 * 3 + i] * Qs[2 * 3 + j];
        float Rxx = R[0][0], Ryy = R[1][1], Rzz = R[2][2];
        float mx = 0.5f * sqrtf(fabsf(1.f + Rxx - Ryy - Rzz));
        float my = 0.5f * sqrtf(fabsf(1.f - Rxx + Ryy - Rzz));
        float mz = 0.5f * sqrtf(fabsf(1.f - Rxx - Ryy + Rzz));
        float x = sgnf(R[2][1] - R[1][2]) * mx;
        float y = sgnf(R[0][2] - R[2][0]) * my;
        float z = sgnf(R[1][0] - R[0][1]) * mz;
        float w = sqrtf(fmaxf(0.f, 1.f + Rxx + Ryy + Rzz)) * 0.5f;
        float nrm = sqrtf(x * x + y * y + z * z + w * w);
        float inv = 1.f / fmaxf(nrm, 1e-12f);
        SET_HALF(hb, 54, x * inv * m);
        SET_HALF(hb, 55, y * inv * m);
        SET_HALF(hb, 56, z * inv * m);
        SET_HALF(hb, 57, w * inv * m);
    }

    // store 16B groups: half0 -> cols 0..55 (7 groups), half1 -> cols 56..119 (8)
    char* slot0 = smem;
    char* slot1 = smem + 16384;
    uint32_t base_col = half ? 56u : 0u;
    int ng = half ? 8 : 7;
    #pragma unroll
    for (int g = 0; g < 8; g++) {
        if (g < ng) {
            uint32_t colg = base_col + g * 8;
            char* sp = (colg < 64) ? slot0 : slot1;
            uint32_t cin = colg & 63;
            uint4 val = make_uint4(hb[g * 4], hb[g * 4 + 1], hb[g * 4 + 2], hb[g * 4 + 3]);
            *(uint4*)(sp + swz((uint32_t)(e * 128 + cin * 2))) = val;
        }
    }
    if (!half) {
        // zero the never-written tail cols 120..127 of chunk 10 (pad weights)
        *(uint4*)(slot1 + swz((uint32_t)(e * 128 + 56 * 2))) = make_uint4(0, 0, 0, 0);
    }
}

// rbf chunks only (c = 0..8)
__device__ __forceinline__ void produce_A(char* smem, int b, int c, int tid)
{
    char* aBuf = smem + b * 16384;
    const float* s_D = (const float*)(smem + SD_OFF);
    const float DLc = 16.f / 15.f;
    const float DL2 = DLc * DLc;
    const float qc  = expf(-2.f * DL2);
    #pragma unroll
    for (int ii = 0; ii < 2; ii++) {
        int inst = tid + ii * 256;
        int pi = inst >> 7;
        int m  = inst & 127;
        float D  = s_D[(c * 4 + pi) * 128 + m];
        float t_ = 0.8f * D;
        float v  = expf(-t_ * t_);
        float r  = expf(2.f * DLc * t_ - DL2);
        uint32_t rowoff = (uint32_t)(m * 128 + pi * 32);
        #pragma unroll
        for (int k = 0; k < 16; k += 4) {
            float v0 = v; v *= r; r *= qc;
            float v1 = v; v *= r; r *= qc;
            float v2 = v; v *= r; r *= qc;
            float v3 = v; v *= r; r *= qc;
            uint2 hh;
            hh.x = packh2(v0, v1);
            hh.y = packh2(v2, v3);
            *(uint2*)(aBuf + swz(rowoff + k * 2)) = hh;
        }
    }
}

// ---- software-pipelined consume: prefetch next LDSM before current MMAs ----
__device__ __forceinline__ void ldA2(uint32_t* dst, uint32_t aBase, int m_base,
                                     int arow, int akoff, int k16)
{
    #pragma unroll
    for (int mblk = 0; mblk < 2; mblk++) {
        uint32_t off = swz((uint32_t)((m_base + mblk * 16 + arow) * 128
                                      + (k16 * 16 + akoff) * 2));
        ldm_x4(dst + mblk * 4, aBase + off);
    }
}
__device__ __forceinline__ void ldB1(uint32_t* dst, uint32_t bBase, int n_base,
                                     int brow, int bkoff, int k16, int np)
{
    uint32_t off = swz((uint32_t)((n_base + np * 16 + brow) * 128
                                  + (k16 * 16 + bkoff) * 2));
    ldm_x4(dst, bBase + off);
}

__device__ __forceinline__ void consume_chunk(uint32_t aBase, uint32_t bBase,
                                              float acc[2][8][4],
                                              int m_base, int n_base, int lane)
{
    int g     = lane >> 3;
    int arow  = (g & 1) * 8 + (lane & 7);
    int akoff = (g >> 1) * 8;
    int brow  = (g >> 1) * 8 + (lane & 7);
    int bkoff = (g & 1) * 8;

    uint32_t aF[2][8], bF[2][4];
    ldA2(aF[0], aBase, m_base, arow, akoff, 0);
    ldB1(bF[0], bBase, n_base, brow, bkoff, 0, 0);

    #pragma unroll
    for (int k16 = 0; k16 < 4; k16++) {
        const int ab = k16 & 1;
        #pragma unroll
        for (int np = 0; np < 4; np++) {
            const int bb = np & 1;
            if (np == 0 && k16 < 3)
                ldA2(aF[ab ^ 1], aBase, m_base, arow, akoff, k16 + 1);
            if (np < 3)
                ldB1(bF[bb ^ 1], bBase, n_base, brow, bkoff, k16, np + 1);
            else if (k16 < 3)
                ldB1(bF[bb ^ 1], bBase, n_base, brow, bkoff, k16 + 1, 0);
            #pragma unroll
            for (int mblk = 0; mblk < 2; mblk++)
                #pragma unroll
                for (int ns = 0; ns < 2; ns++)
                    mma_fp16(acc[mblk][np * 2 + ns], aF[ab] + mblk * 4, bF[bb] + ns * 2);
        }
    }
}

__global__ void __launch_bounds__(256, 2)
edge_fused_kernel(const float* __restrict__ coords,
                  const int*   __restrict__ eidx,
                  const float* __restrict__ bias,
                  const float* __restrict__ lnw,
                  const float* __restrict__ lnb,
                  float* __restrict__ out,
                  int n_edges)
{
    extern __shared__ char smem[];
    const uint32_t sb = smem_to_u32(smem);
    const int tid = threadIdx.x;
    const int e0  = blockIdx.x * 128;
    float2* s_red = (float2*)(smem + RED_OFF);

    const int w      = tid >> 5;
    const int lane   = tid & 31;
    const int m_base = (w & 3) * 32;
    const int nh     = w >> 2;
    const int n_base = nh * 64;

    // chunk order: 9 (staged slot0), 10 (staged slot1), then rbf 0..8
    produce_B_async(sb, 0, 9, tid);
    stage_tile(smem, coords, eidx, n_edges, e0, tid);

    float acc[2][8][4];
    #pragma unroll
    for (int i = 0; i < 2; i++)
        #pragma unroll
        for (int j = 0; j < 8; j++)
            #pragma unroll
            for (int k = 0; k < 4; k++) acc[i][j][k] = 0.f;

    cp_async_wait0();
    __syncthreads();
    #pragma unroll 1
    for (int i = 0; i < 11; i++) {
        int slot = i & 1;
        if (i + 1 < 11) {
            int nc = (i == 0) ? 10 : (i - 1);   // order[i+1]
            produce_B_async(sb, (i + 1) & 1, nc, tid);
        }
        consume_chunk(sb + slot * 16384, sb + SB_OFF + slot * 16384,
                      acc, m_base, n_base, lane);
        if (i + 1 < 11) {
            if (i >= 1) produce_A(smem, (i + 1) & 1, i - 1, tid);
            cp_async_wait0();
        }
        __syncthreads();
    }

    // ---- epilogue: bias + layernorm ----
    const int qr = lane >> 2, qc2 = lane & 3;
    float s1[2][2] = {{0.f,0.f},{0.f,0.f}}, s2[2][2] = {{0.f,0.f},{0.f,0.f}};
    #pragma unroll
    for (int mblk = 0; mblk < 2; mblk++)
        #pragma unroll
        for (int nb = 0; nb < 8; nb++) {
            int col = n_base + nb * 8 + qc2 * 2;
            float b0 = bias[col], b1 = bias[col + 1];
            #pragma unroll
            for (int rh = 0; rh < 2; rh++) {
                float v0 = acc[mblk][nb][rh * 2]     + b0;
                float v1 = acc[mblk][nb][rh * 2 + 1] + b1;
                acc[mblk][nb][rh * 2]     = v0;
                acc[mblk][nb][rh * 2 + 1] = v1;
                s1[mblk][rh] += v0 + v1;
                s2[mblk][rh] += v0 * v0 + v1 * v1;
            }
        }
    #pragma unroll
    for (int mblk = 0; mblk < 2; mblk++)
        #pragma unroll
        for (int rh = 0; rh < 2; rh++) {
            #pragma unroll
            for (int o = 1; o < 4; o <<= 1) {
                s1[mblk][rh] += __shfl_xor_sync(0xffffffffu, s1[mblk][rh], o);
                s2[mblk][rh] += __shfl_xor_sync(0xffffffffu, s2[mblk][rh], o);
            }
        }
    if (qc2 == 0) {
        #pragma unroll
        for (int mblk = 0; mblk < 2; mblk++)
            #pragma unroll
            for (int rh = 0; rh < 2; rh++) {
                int row = m_base + mblk * 16 + qr + rh * 8;
                s_red[row * 2 + nh] = make_float2(s1[mblk][rh], s2[mblk][rh]);
            }
    }
    __syncthreads();
    #pragma unroll
    for (int mblk = 0; mblk < 2; mblk++)
        #pragma unroll
        for (int rh = 0; rh < 2; rh++) {
            int row = m_base + mblk * 16 + qr + rh * 8;
            float2 r0 = s_red[row * 2], r1 = s_red[row * 2 + 1];
            float S1 = r0.x + r1.x, S2 = r0.y + r1.y;
            float mu  = S1 * (1.f / 128.f);
            float var = S2 * (1.f / 128.f) - mu * mu;
            float rs  = rsqrtf(var + 1e-5f);
            int ge = e0 + row;
            if (ge < n_edges) {
                #pragma unroll
                for (int nb = 0; nb < 8; nb++) {
                    int col = n_base + nb * 8 + qc2 * 2;
                    float2 o;
                    o.x = (acc[mblk][nb][rh * 2]     - mu) * rs * lnw[col]     + lnb[col];
                    o.y = (acc[mblk][nb][rh * 2 + 1] - mu) * rs * lnw[col + 1] + lnb[col + 1];
                    *(float2*)(out + (size_t)ge * HID + col) = o;
                }
            }
        }
}

// =====================================================================
extern "C" void kernel_launch(void* const* d_in, const int* in_sizes, int n_in,
                              void* d_out, int out_size)
{
    const float* coords = (const float*)d_in[0];
    const float* cX     = (const float*)d_in[1];
    const float* nW     = (const float*)d_in[2];
    const float* nb     = (const float*)d_in[3];
    const float* nlw    = (const float*)d_in[4];
    const float* nlb    = (const float*)d_in[5];
    const float* eW     = (const float*)d_in[6];
    const float* ebias  = (const float*)d_in[7];
    const float* elw    = (const float*)d_in[8];
    const float* elb    = (const float*)d_in[9];
    const int*   batch  = (const int*)d_in[10];
    const int*   eidx   = (const int*)d_in[11];

    int n_res   = in_sizes[0] / (N_ATOMS * 3);
    int n_edges = in_sizes[11] / 2;
    int tiles   = (n_edges + 127) / 128;
    float* out  = (float*)d_out;

    cudaFuncSetAttribute(edge_fused_kernel,
                         cudaFuncAttributeMaxDynamicSharedMemorySize, SMEM_TOT);

    node_fused_kernel<<<(n_res + 127) / 128, 128>>>(coords, cX, batch,
                                                    nW, nb, nlw, nlb, out, n_res);
    bprep_kernel<<<N_CHUNKS, 256>>>(eW);
    edge_fused_kernel<<<tiles, 256, SMEM_TOT>>>(coords, eidx, ebias, elw, elb,
                                                out + (size_t)n_res * HID, n_edges);
}

// round 16
// speedup vs baseline: 1.1111x; 1.1111x over previous
#include <cuda_runtime.h>
#include <cuda_bf16.h>
#include <cuda_fp16.h>
#include <cstdint>
#include <math.h>

#define N_RES_MAX 30000
#define N_ATOMS   6
#define HID       128
#define N_CHUNKS  11

// ---- scratch (device globals; no allocations allowed) ----
__device__ float         g_Q[N_RES_MAX * 9];
__device__ unsigned char g_valid[N_RES_MAX];
__device__ float         g_nodeFeat[N_RES_MAX * 44];
__device__ unsigned char g_Bimg[N_CHUNKS * 16384];       // pre-swizzled W chunks (fp16, 16KB each)

// =====================================================================
// helpers
// =====================================================================
__device__ __forceinline__ uint32_t smem_to_u32(const void* p) {
    uint32_t a;
    asm("{ .reg .u64 t; cvta.to.shared.u64 t, %1; cvt.u32.u64 %0, t; }" : "=r"(a) : "l"(p));
    return a;
}
__device__ __forceinline__ uint32_t swz(uint32_t off) { return off ^ ((off >> 3) & 0x70); }
__device__ __forceinline__ uint32_t packh2(float a, float b) {
    __half2 h = __floats2half2_rn(a, b);
    return *(uint32_t*)&h;
}
__device__ __forceinline__ float sgnf(float x) {
    return (x > 0.f) ? 1.f : ((x < 0.f) ? -1.f : 0.f);
}
__device__ __forceinline__ void norm3(float& x, float& y, float& z) {
    float n = sqrtf(x * x + y * y + z * z);
    float inv = 1.f / fmaxf(n, 1e-12f);
    x *= inv; y *= inv; z *= inv;
}
__device__ __forceinline__ void ldm_x4(uint32_t* r, uint32_t addr) {
    asm volatile("ldmatrix.sync.aligned.m8n8.x4.shared.b16 {%0,%1,%2,%3}, [%4];"
        : "=r"(r[0]), "=r"(r[1]), "=r"(r[2]), "=r"(r[3]) : "r"(addr));
}
__device__ __forceinline__ void mma_fp16(float* c, const uint32_t* a, const uint32_t* b) {
    asm volatile("mma.sync.aligned.m16n8k16.row.col.f32.f16.f16.f32 "
        "{%0,%1,%2,%3}, {%4,%5,%6,%7}, {%8,%9}, {%0,%1,%2,%3};"
        : "+f"(c[0]), "+f"(c[1]), "+f"(c[2]), "+f"(c[3])
        : "r"(a[0]), "r"(a[1]), "r"(a[2]), "r"(a[3]), "r"(b[0]), "r"(b[1]));
}
__device__ __forceinline__ void cp_async16(uint32_t smem_dst, const void* gsrc) {
    asm volatile("cp.async.cg.shared.global [%0], [%1], 16;"
        :: "r"(smem_dst), "l"(gsrc) : "memory");
}
__device__ __forceinline__ void cp_async_commit() {
    asm volatile("cp.async.commit_group;" ::: "memory");
}
__device__ __forceinline__ void cp_async_wait0() {
    asm volatile("cp.async.wait_group 0;" ::: "memory");
}

// set half #idx inside packed uint array (idx must be compile-time under unroll)
#define SET_HALF(arr, idx, f) do {                                        \
    uint32_t hv = (uint32_t)__half_as_ushort(__float2half(f));            \
    if ((idx) & 1) (arr)[(idx) >> 1] |= (hv << 16);                       \
    else           (arr)[(idx) >> 1] |= hv;                               \
} while (0)

// =====================================================================
// Kernel 1: per-residue node features (44) + Q frames + validity
// =====================================================================
__global__ void node_feat_kernel(const float* __restrict__ coords,
                                 const float* __restrict__ cX,
                                 const int*   __restrict__ batch,
                                 int n_res)
{
    int r = blockIdx.x * blockDim.x + threadIdx.x;
    if (r >= n_res) return;
    const int L = n_res * N_ATOMS;

    bool bnd  = (r > 0)         && (batch[r]     != batch[r - 1]);
    bool bndn = (r < n_res - 1) && (batch[r + 1] != batch[r]);

    float xp[9][3];
    #pragma unroll
    for (int i = 0; i < 9; i++) {
        int j = 6 * r + i - 1;
        j = max(0, min(L - 1, j));
        xp[i][0] = coords[j * 3 + 0];
        xp[i][1] = coords[j * 3 + 1];
        xp[i][2] = coords[j * 3 + 2];
    }
    float U[8][3];
    #pragma unroll
    for (int i = 0; i < 8; i++) {
        float dx = xp[i + 1][0] - xp[i][0];
        float dy = xp[i + 1][1] - xp[i][1];
        float dz = xp[i + 1][2] - xp[i][2];
        norm3(dx, dy, dz);
        U[i][0] = dx; U[i][1] = dy; U[i][2] = dz;
    }

    float feat[44];
    #pragma unroll
    for (int a = 0; a < 6; a++) {
        int j = 6 * r + a;
        bool dm = (j >= 1) && (j <= L - 3) && !(bnd && a == 0) && !(bndn && a >= 4);
        float sv = 0.f, cv = 0.f;
        if (dm) {
            float c1x = U[a][1] * U[a + 1][2] - U[a][2] * U[a + 1][1];
            float c1y = U[a][2] * U[a + 1][0] - U[a][0] * U[a + 1][2];
            float c1z = U[a][0] * U[a + 1][1] - U[a][1] * U[a + 1][0];
            norm3(c1x, c1y, c1z);
            float c2x = U[a + 1][1] * U[a + 2][2] - U[a + 1][2] * U[a + 2][1];
            float c2y = U[a + 1][2] * U[a + 2][0] - U[a + 1][0] * U[a + 2][2];
            float c2z = U[a + 1][0] * U[a + 2][1] - U[a + 1][1] * U[a + 2][0];
            norm3(c2x, c2y, c2z);
            float d = c1x * c2x + c1y * c2y + c1z * c2z;
            d = fminf(fmaxf(d, -1.f + 1e-6f), 1.f - 1e-6f);
            float sg = sgnf(c2x * U[a][0] + c2y * U[a][1] + c2z * U[a][2]);
            float dih = acosf(d) * sg;
            sv = sinf(dih); cv = cosf(dih);
        }
        feat[2 * a]     = sv;
        feat[2 * a + 1] = cv;
        bool am = (j >= 1) && (j <= L - 2) && !(bnd && a == 0) && !(bndn && a == 5);
        float sa = 0.f, ca = 0.f;
        if (am) {
            float ax = xp[a][0] - xp[a + 1][0];
            float ay = xp[a][1] - xp[a + 1][1];
            float az = xp[a][2] - xp[a + 1][2];
            norm3(ax, ay, az);
            float bx = xp[a + 2][0] - xp[a + 1][0];
            float by = xp[a + 2][1] - xp[a + 1][1];
            float bz = xp[a + 2][2] - xp[a + 1][2];
            norm3(bx, by, bz);
            ca = ax * bx + ay * by + az * bz;
            sa = sqrtf(1.f - ca * ca + 1e-6f);
        }
        feat[12 + 2 * a] = sa;
        feat[13 + 2 * a] = ca;
    }

    float Q[3][3] = {{0.f,0.f,0.f},{0.f,0.f,0.f},{0.f,0.f,0.f}};
    bool qv = false;
    float cx0[3] = { cX[r * 3 + 0], cX[r * 3 + 1], cX[r * 3 + 2] };
    if (r >= 1 && r <= n_res - 2) {
        float cm[3] = { cX[(r - 1) * 3 + 0], cX[(r - 1) * 3 + 1], cX[(r - 1) * 3 + 2] };
        float cp[3] = { cX[(r + 1) * 3 + 0], cX[(r + 1) * 3 + 1], cX[(r + 1) * 3 + 2] };
        float u0x = cx0[0] - cm[0], u0y = cx0[1] - cm[1], u0z = cx0[2] - cm[2];
        norm3(u0x, u0y, u0z);
        float u1x = cp[0] - cx0[0], u1y = cp[1] - cx0[1], u1z = cp[2] - cx0[2];
        norm3(u1x, u1y, u1z);
        float bx = u0x - u1x, by = u0y - u1y, bz = u0z - u1z;
        norm3(bx, by, bz);
        float nx = u0y * u1z - u0z * u1y;
        float ny = u0z * u1x - u0x * u1z;
        float nz = u0x * u1y - u0y * u1x;
        norm3(nx, ny, nz);
        float ccx = by * nz - bz * ny;
        float ccy = bz * nx - bx * nz;
        float ccz = bx * ny - by * nx;
        qv = !bnd && !bndn;
        float m = qv ? 1.f : 0.f;
        Q[0][0] = bx * m; Q[0][1] = nx * m; Q[0][2] = ccx * m;
        Q[1][0] = by * m; Q[1][1] = ny * m; Q[1][2] = ccy * m;
        Q[2][0] = bz * m; Q[2][1] = nz * m; Q[2][2] = ccz * m;
    }
    g_valid[r] = qv ? 1 : 0;
    #pragma unroll
    for (int k = 0; k < 3; k++)
        #pragma unroll
        for (int j = 0; j < 3; j++)
            g_Q[r * 9 + k * 3 + j] = Q[k][j];

    const int keep[5] = {0, 2, 3, 4, 5};
    #pragma unroll
    for (int ai = 0; ai < 5; ai++) {
        int a = keep[ai];
        float dx = xp[a + 1][0] - cx0[0];
        float dy = xp[a + 1][1] - cx0[1];
        float dz = xp[a + 1][2] - cx0[2];
        float ss = dx * dx + dy * dy + dz * dz;
        feat[24 + ai] = 0.5f * logf(ss + 1e-6f);
        float inv = 1.f / fmaxf(sqrtf(ss), 1e-12f);
        float nx = dx * inv, ny = dy * inv, nz = dz * inv;
        #pragma unroll
        for (int i = 0; i < 3; i++)
            feat[29 + ai * 3 + i] = Q[0][i] * nx + Q[1][i] * ny + Q[2][i] * nz;
    }
    #pragma unroll
    for (int k = 0; k < 44; k++)
        g_nodeFeat[r * 44 + k] = feat[k];
}

// =====================================================================
// Kernel 2: node matvec (44->128) + bias + layernorm. One warp per residue.
// =====================================================================
__global__ void node_gemm_kernel(const float* __restrict__ W,
                                 const float* __restrict__ b,
                                 const float* __restrict__ lnw,
                                 const float* __restrict__ lnb,
                                 float* __restrict__ out,
                                 int n_res)
{
    int gw   = (blockIdx.x * blockDim.x + threadIdx.x) >> 5;
    int lane = threadIdx.x & 31;
    if (gw >= n_res) return;
    const float* f = g_nodeFeat + gw * 44;

    float acc[4];
    #pragma unroll
    for (int u = 0; u < 4; u++) acc[u] = b[lane + 32 * u];
    #pragma unroll 4
    for (int k = 0; k < 44; k++) {
        float fv = f[k];
        #pragma unroll
        for (int u = 0; u < 4; u++)
            acc[u] += fv * W[k * HID + lane + 32 * u];
    }
    float s1 = acc[0] + acc[1] + acc[2] + acc[3];
    float s2 = acc[0]*acc[0] + acc[1]*acc[1] + acc[2]*acc[2] + acc[3]*acc[3];
    #pragma unroll
    for (int o = 16; o > 0; o >>= 1) {
        s1 += __shfl_xor_sync(0xffffffffu, s1, o);
        s2 += __shfl_xor_sync(0xffffffffu, s2, o);
    }
    float mu  = s1 * (1.f / 128.f);
    float var = s2 * (1.f / 128.f) - mu * mu;
    float rs  = rsqrtf(var + 1e-5f);
    #pragma unroll
    for (int u = 0; u < 4; u++) {
        int c = lane + 32 * u;
        out[(size_t)gw * HID + c] = (acc[u] - mu) * rs * lnw[c] + lnb[c];
    }
}

// =====================================================================
// Kernel 3: W prep — pre-swizzled SW128 fp16 image per 64-K chunk (16KB)
// Plane order: k 0..575 rbf (feature 4+k);  k 576..703: col = k-576:
//   col 0..53   -> dir feature 580+col        (half0 planes)
//   col 54..55  -> pad (0)
//   col 56..109 -> dir feature 634+(col-56)   (half1 planes)
//   col 110..113-> quat feature col-110
//   col 114..127-> pad (0)
// =====================================================================
__device__ __forceinline__ int feat_of_k(int k) {
    if (k < 576) return 4 + k;
    int col = k - 576;
    if (col < 54)  return 580 + col;
    if (col < 56)  return -1;
    if (col < 110) return 634 + (col - 56);
    if (col < 114) return col - 110;
    return -1;
}

__global__ void bprep_kernel(const float* __restrict__ eW)
{
    int c = blockIdx.x;
    char* img = (char*)(g_Bimg + (size_t)c * 16384);
    for (int i = threadIdx.x; i < 4096; i += blockDim.x) {
        int n = i >> 5, kp = i & 31;            // kp = pair of k
        int k0 = c * 64 + kp * 2;
        int fa = feat_of_k(k0), fb = feat_of_k(k0 + 1);
        float w0 = (fa >= 0) ? eW[fa * HID + n] : 0.f;
        float w1 = (fb >= 0) ? eW[fb * HID + n] : 0.f;
        *(uint32_t*)(img + swz((uint32_t)(n * 128 + kp * 4))) = packh2(w0, w1);
    }
}

// =====================================================================
// Kernel 4 (FUSED edge): features + GEMM + bias + layernorm.
// M=128 edges/CTA, N=128, K=704 in 11 chunks, order [9,10,0..8];
// chunks 9/10 staged directly into the A double-buffer. 2 CTAs/SM.
// Software-pipelined consume (register-double-buffered LDSM).
// smem: A[2]@0,16384 | B[2]@32768,49152 | D(36 planes f32)@65536 |
//       red(2KB)@83968.   total 86016 B
// =====================================================================
#define SB_OFF   32768
#define SD_OFF   65536
#define RED_OFF  83968
#define SMEM_TOT 86016

__device__ __forceinline__ void produce_B_async(uint32_t sb, int b, int c, int tid)
{
    const char* src = (const char*)(g_Bimg + (size_t)c * 16384);
    uint32_t dst = sb + SB_OFF + b * 16384;
    #pragma unroll
    for (int i = 0; i < 4; i++)
        cp_async16(dst + (tid + i * 256) * 16, src + (tid + i * 256) * 16);
    cp_async_commit();
}

// ---- per-tile staging: 2 threads/edge; dirs+quat go straight into the
//      swizzled A buffers (slot0 = chunk 9, slot1 = chunk 10) ----
__device__ __forceinline__ void stage_tile(char* smem,
                                           const float* __restrict__ coords,
                                           const int*   __restrict__ eidx,
                                           int n_edges, int e0, int tid)
{
    float* s_D = (float*)(smem + SD_OFF);
    int e = tid >> 1, half = tid & 1;
    int ge = min(e0 + e, n_edges - 1);
    int s = eidx[ge], t = eidx[n_edges + ge];

    float Qt[9];
    #pragma unroll
    for (int i = 0; i < 9; i++) Qt[i] = g_Q[t * 9 + i];
    float ct[9];
    #pragma unroll
    for (int j = 0; j < 9; j++) ct[j] = coords[t * 18 + half * 9 + j];
    float cs[18];
    #pragma unroll
    for (int j = 0; j < 18; j++) cs[j] = coords[s * 18 + j];

    uint32_t hb[32];
    #pragma unroll
    for (int j = 0; j < 32; j++) hb[j] = 0;

    #pragma unroll
    for (int pp = 0; pp < 18; pp++) {
        int tl = pp / 6, sa = pp % 6;
        int p  = half * 18 + pp;                 // global pair index ta*6+sa
        float dx = cs[sa * 3 + 0] - ct[tl * 3 + 0];
        float dy = cs[sa * 3 + 1] - ct[tl * 3 + 1];
        float dz = cs[sa * 3 + 2] - ct[tl * 3 + 2];
        float ss2 = dx * dx + dy * dy + dz * dz;
        s_D[p * 128 + e] = sqrtf(ss2 + 1e-6f);
        float inv = 1.f / fmaxf(sqrtf(ss2), 1e-12f);
        float nx = dx * inv, ny = dy * inv, nz = dz * inv;
        float v0 = Qt[0] * nx + Qt[3] * ny + Qt[6] * nz;
        float v1 = Qt[1] * nx + Qt[4] * ny + Qt[7] * nz;
        float v2 = Qt[2] * nx + Qt[5] * ny + Qt[8] * nz;
        SET_HALF(hb, pp * 3 + 0, v0);
        SET_HALF(hb, pp * 3 + 1, v1);
        SET_HALF(hb, pp * 3 + 2, v2);
    }

    if (half) {
        // quaternion appended at local positions 54..57
        float Qs[9];
        #pragma unroll
        for (int i = 0; i < 9; i++) Qs[i] = g_Q[s * 9 + i];
        float m = (g_valid[s] && g_valid[t]) ? 1.f : 0.f;
        float R[3][3];
        #pragma unroll
        for (int i = 0; i < 3; i++)
            #pragma unroll
            for (int j = 0; j < 3; j++)
                R[i][j] = Qt[0 * 3 + i] * Qs[0 * 3 + j]
                        + Qt[1 * 3 + i] * Qs[1 * 3 + j]
                        + Qt[2 * 3 + i] * Qs[2 * 3 + j];
        float Rxx = R[0][0], Ryy = R[1][1], Rzz = R[2][2];
        float mx = 0.5f * sqrtf(fabsf(1.f + Rxx - Ryy - Rzz));
        float my = 0.5f * sqrtf(fabsf(1.f - Rxx + Ryy - Rzz));
        float mz = 0.5f * sqrtf(fabsf(1.f - Rxx - Ryy + Rzz));
        float x = sgnf(R[2][1] - R[1][2]) * mx;
        float y = sgnf(R[0][2] - R[2][0]) * my;
        float z = sgnf(R[1][0] - R[0][1]) * mz;
        float w = sqrtf(fmaxf(0.f, 1.f + Rxx + Ryy + Rzz)) * 0.5f;
        float nrm = sqrtf(x * x + y * y + z * z + w * w);
        float inv = 1.f / fmaxf(nrm, 1e-12f);
        SET_HALF(hb, 54, x * inv * m);
        SET_HALF(hb, 55, y * inv * m);
        SET_HALF(hb, 56, z * inv * m);
        SET_HALF(hb, 57, w * inv * m);
    }

    // store 16B groups: half0 -> cols 0..55 (7 groups), half1 -> cols 56..119 (8)
    char* slot0 = smem;
    char* slot1 = smem + 16384;
    uint32_t base_col = half ? 56u : 0u;
    int ng = half ? 8 : 7;
    #pragma unroll
    for (int g = 0; g < 8; g++) {
        if (g < ng) {
            uint32_t colg = base_col + g * 8;
            char* sp = (colg < 64) ? slot0 : slot1;
            uint32_t cin = colg & 63;
            uint4 val = make_uint4(hb[g * 4], hb[g * 4 + 1], hb[g * 4 + 2], hb[g * 4 + 3]);
            *(uint4*)(sp + swz((uint32_t)(e * 128 + cin * 2))) = val;
        }
    }
    if (!half) {
        // zero the never-written tail cols 120..127 of chunk 10 (pad weights)
        *(uint4*)(slot1 + swz((uint32_t)(e * 128 + 56 * 2))) = make_uint4(0, 0, 0, 0);
    }
}

// rbf chunks only (c = 0..8)
__device__ __forceinline__ void produce_A(char* smem, int b, int c, int tid)
{
    char* aBuf = smem + b * 16384;
    const float* s_D = (const float*)(smem + SD_OFF);
    const float DLc = 16.f / 15.f;
    const float DL2 = DLc * DLc;
    const float qc  = expf(-2.f * DL2);
    #pragma unroll
    for (int ii = 0; ii < 2; ii++) {
        int inst = tid + ii * 256;
        int pi = inst >> 7;
        int m  = inst & 127;
        float D  = s_D[(c * 4 + pi) * 128 + m];
        float t_ = 0.8f * D;
        float v  = expf(-t_ * t_);
        float r  = expf(2.f * DLc * t_ - DL2);
        uint32_t rowoff = (uint32_t)(m * 128 + pi * 32);
        #pragma unroll
        for (int k = 0; k < 16; k += 4) {
            float v0 = v; v *= r; r *= qc;
            float v1 = v; v *= r; r *= qc;
            float v2 = v; v *= r; r *= qc;
            float v3 = v; v *= r; r *= qc;
            uint2 hh;
            hh.x = packh2(v0, v1);
            hh.y = packh2(v2, v3);
            *(uint2*)(aBuf + swz(rowoff + k * 2)) = hh;
        }
    }
}

// ---- software-pipelined consume: prefetch next LDSM before current MMAs ----
__device__ __forceinline__ void ldA2(uint32_t* dst, uint32_t aBase, int m_base,
                                     int arow, int akoff, int k16)
{
    #pragma unroll
    for (int mblk = 0; mblk < 2; mblk++) {
        uint32_t off = swz((uint32_t)((m_base + mblk * 16 + arow) * 128
                                      + (k16 * 16 + akoff) * 2));
        ldm_x4(dst + mblk * 4, aBase + off);
    }
}
__device__ __forceinline__ void ldB1(uint32_t* dst, uint32_t bBase, int n_base,
                                     int brow, int bkoff, int k16, int np)
{
    uint32_t off = swz((uint32_t)((n_base + np * 16 + brow) * 128
                                  + (k16 * 16 + bkoff) * 2));
    ldm_x4(dst, bBase + off);
}

__device__ __forceinline__ void consume_chunk(uint32_t aBase, uint32_t bBase,
                                              float acc[2][8][4],
                                              int m_base, int n_base, int lane)
{
    int g     = lane >> 3;
    int arow  = (g & 1) * 8 + (lane & 7);
    int akoff = (g >> 1) * 8;
    int brow  = (g >> 1) * 8 + (lane & 7);
    int bkoff = (g & 1) * 8;

    uint32_t aF[2][8], bF[2][4];
    ldA2(aF[0], aBase, m_base, arow, akoff, 0);
    ldB1(bF[0], bBase, n_base, brow, bkoff, 0, 0);

    #pragma unroll
    for (int k16 = 0; k16 < 4; k16++) {
        const int ab = k16 & 1;
        #pragma unroll
        for (int np = 0; np < 4; np++) {
            const int bb = np & 1;
            if (np == 0 && k16 < 3)
                ldA2(aF[ab ^ 1], aBase, m_base, arow, akoff, k16 + 1);
            if (np < 3)
                ldB1(bF[bb ^ 1], bBase, n_base, brow, bkoff, k16, np + 1);
            else if (k16 < 3)
                ldB1(bF[bb ^ 1], bBase, n_base, brow, bkoff, k16 + 1, 0);
            #pragma unroll
            for (int mblk = 0; mblk < 2; mblk++)
                #pragma unroll
                for (int ns = 0; ns < 2; ns++)
                    mma_fp16(acc[mblk][np * 2 + ns], aF[ab] + mblk * 4, bF[bb] + ns * 2);
        }
    }
}

__global__ void __launch_bounds__(256, 2)
edge_fused_kernel(const float* __restrict__ coords,
                  const int*   __restrict__ eidx,
                  const float* __restrict__ bias,
                  const float* __restrict__ lnw,
                  const float* __restrict__ lnb,
                  float* __restrict__ out,
                  int n_edges)
{
    extern __shared__ char smem[];
    const uint32_t sb = smem_to_u32(smem);
    const int tid = threadIdx.x;
    const int e0  = blockIdx.x * 128;
    float2* s_red = (float2*)(smem + RED_OFF);

    const int w      = tid >> 5;
    const int lane   = tid & 31;
    const int m_base = (w & 3) * 32;
    const int nh     = w >> 2;
    const int n_base = nh * 64;

    // chunk order: 9 (staged slot0), 10 (staged slot1), then rbf 0..8
    produce_B_async(sb, 0, 9, tid);
    stage_tile(smem, coords, eidx, n_edges, e0, tid);

    float acc[2][8][4];
    #pragma unroll
    for (int i = 0; i < 2; i++)
        #pragma unroll
        for (int j = 0; j < 8; j++)
            #pragma unroll
            for (int k = 0; k < 4; k++) acc[i][j][k] = 0.f;

    cp_async_wait0();
    __syncthreads();
    #pragma unroll 1
    for (int i = 0; i < 11; i++) {
        int slot = i & 1;
        if (i + 1 < 11) {
            int nc = (i == 0) ? 10 : (i - 1);   // order[i+1]
            produce_B_async(sb, (i + 1) & 1, nc, tid);
        }
        consume_chunk(sb + slot * 16384, sb + SB_OFF + slot * 16384,
                      acc, m_base, n_base, lane);
        if (i + 1 < 11) {
            if (i >= 1) produce_A(smem, (i + 1) & 1, i - 1, tid);
            cp_async_wait0();
        }
        __syncthreads();
    }

    // ---- epilogue: bias + layernorm ----
    const int qr = lane >> 2, qc2 = lane & 3;
    float s1[2][2] = {{0.f,0.f},{0.f,0.f}}, s2[2][2] = {{0.f,0.f},{0.f,0.f}};
    #pragma unroll
    for (int mblk = 0; mblk < 2; mblk++)
        #pragma unroll
        for (int nb = 0; nb < 8; nb++) {
            int col = n_base + nb * 8 + qc2 * 2;
            float b0 = bias[col], b1 = bias[col + 1];
            #pragma unroll
            for (int rh = 0; rh < 2; rh++) {
                float v0 = acc[mblk][nb][rh * 2]     + b0;
                float v1 = acc[mblk][nb][rh * 2 + 1] + b1;
                acc[mblk][nb][rh * 2]     = v0;
                acc[mblk][nb][rh * 2 + 1] = v1;
                s1[mblk][rh] += v0 + v1;
                s2[mblk][rh] += v0 * v0 + v1 * v1;
            }
        }
    #pragma unroll
    for (int mblk = 0; mblk < 2; mblk++)
        #pragma unroll
        for (int rh = 0; rh < 2; rh++) {
            #pragma unroll
            for (int o = 1; o < 4; o <<= 1) {
                s1[mblk][rh] += __shfl_xor_sync(0xffffffffu, s1[mblk][rh], o);
                s2[mblk][rh] += __shfl_xor_sync(0xffffffffu, s2[mblk][rh], o);
            }
        }
    if (qc2 == 0) {
        #pragma unroll
        for (int mblk = 0; mblk < 2; mblk++)
            #pragma unroll
            for (int rh = 0; rh < 2; rh++) {
                int row = m_base + mblk * 16 + qr + rh * 8;
                s_red[row * 2 + nh] = make_float2(s1[mblk][rh], s2[mblk][rh]);
            }
    }
    __syncthreads();
    #pragma unroll
    for (int mblk = 0; mblk < 2; mblk++)
        #pragma unroll
        for (int rh = 0; rh < 2; rh++) {
            int row = m_base + mblk * 16 + qr + rh * 8;
            float2 r0 = s_red[row * 2], r1 = s_red[row * 2 + 1];
            float S1 = r0.x + r1.x, S2 = r0.y + r1.y;
            float mu  = S1 * (1.f / 128.f);
            float var = S2 * (1.f / 128.f) - mu * mu;
            float rs  = rsqrtf(var + 1e-5f);
            int ge = e0 + row;
            if (ge < n_edges) {
                #pragma unroll
                for (int nb = 0; nb < 8; nb++) {
                    int col = n_base + nb * 8 + qc2 * 2;
                    float2 o;
                    o.x = (acc[mblk][nb][rh * 2]     - mu) * rs * lnw[col]     + lnb[col];
                    o.y = (acc[mblk][nb][rh * 2 + 1] - mu) * rs * lnw[col + 1] + lnb[col + 1];
                    *(float2*)(out + (size_t)ge * HID + col) = o;
                }
            }
        }
}

// =====================================================================
extern "C" void kernel_launch(void* const* d_in, const int* in_sizes, int n_in,
                              void* d_out, int out_size)
{
    const float* coords = (const float*)d_in[0];
    const float* cX     = (const float*)d_in[1];
    const float* nW     = (const float*)d_in[2];
    const float* nb     = (const float*)d_in[3];
    const float* nlw    = (const float*)d_in[4];
    const float* nlb    = (const float*)d_in[5];
    const float* eW     = (const float*)d_in[6];
    const float* ebias  = (const float*)d_in[7];
    const float* elw    = (const float*)d_in[8];
    const float* elb    = (const float*)d_in[9];
    const int*   batch  = (const int*)d_in[10];
    const int*   eidx   = (const int*)d_in[11];

    int n_res   = in_sizes[0] / (N_ATOMS * 3);
    int n_edges = in_sizes[11] / 2;
    int tiles   = (n_edges + 127) / 128;
    float* out  = (float*)d_out;

    cudaFuncSetAttribute(edge_fused_kernel,
                         cudaFuncAttributeMaxDynamicSharedMemorySize, SMEM_TOT);

    node_feat_kernel<<<(n_res + 127) / 128, 128>>>(coords, cX, batch, n_res);
    node_gemm_kernel<<<(n_res + 7) / 8, 256>>>(nW, nb, nlw, nlb, out, n_res);
    bprep_kernel<<<N_CHUNKS, 256>>>(eW);
    edge_fused_kernel<<<tiles, 256, SMEM_TOT>>>(coords, eidx, ebias, elw, elb,
                                                out + (size_t)n_res * HID, n_edges);
}

// round 17
// speedup vs baseline: 1.1763x; 1.0587x over previous
#include <cuda_runtime.h>
#include <cuda_bf16.h>
#include <cuda_fp16.h>
#include <cstdint>
#include <math.h>

#define N_RES_MAX 30000
#define N_ATOMS   6
#define HID       128
#define N_CHUNKS  11

// ---- scratch (device globals; no allocations allowed) ----
__device__ float         g_Q[N_RES_MAX * 9];
__device__ unsigned char g_valid[N_RES_MAX];
__device__ float         g_nodeFeat[N_RES_MAX * 44];
__device__ unsigned char g_Bimg[N_CHUNKS * 16384];       // pre-swizzled W chunks (fp16, 16KB each)

// =====================================================================
// helpers
// =====================================================================
__device__ __forceinline__ uint32_t smem_to_u32(const void* p) {
    uint32_t a;
    asm("{ .reg .u64 t; cvta.to.shared.u64 t, %1; cvt.u32.u64 %0, t; }" : "=r"(a) : "l"(p));
    return a;
}
__device__ __forceinline__ uint32_t swz(uint32_t off) { return off ^ ((off >> 3) & 0x70); }
__device__ __forceinline__ uint32_t packh2(float a, float b) {
    __half2 h = __floats2half2_rn(a, b);
    return *(uint32_t*)&h;
}
__device__ __forceinline__ float sgnf(float x) {
    return (x > 0.f) ? 1.f : ((x < 0.f) ? -1.f : 0.f);
}
__device__ __forceinline__ void norm3(float& x, float& y, float& z) {
    float n = sqrtf(x * x + y * y + z * z);
    float inv = 1.f / fmaxf(n, 1e-12f);
    x *= inv; y *= inv; z *= inv;
}
__device__ __forceinline__ void ldm_x4(uint32_t* r, uint32_t addr) {
    asm volatile("ldmatrix.sync.aligned.m8n8.x4.shared.b16 {%0,%1,%2,%3}, [%4];"
        : "=r"(r[0]), "=r"(r[1]), "=r"(r[2]), "=r"(r[3]) : "r"(addr));
}
__device__ __forceinline__ void mma_fp16(float* c, const uint32_t* a, const uint32_t* b) {
    asm volatile("mma.sync.aligned.m16n8k16.row.col.f32.f16.f16.f32 "
        "{%0,%1,%2,%3}, {%4,%5,%6,%7}, {%8,%9}, {%0,%1,%2,%3};"
        : "+f"(c[0]), "+f"(c[1]), "+f"(c[2]), "+f"(c[3])
        : "r"(a[0]), "r"(a[1]), "r"(a[2]), "r"(a[3]), "r"(b[0]), "r"(b[1]));
}
__device__ __forceinline__ void cp_async16(uint32_t smem_dst, const void* gsrc) {
    asm volatile("cp.async.cg.shared.global [%0], [%1], 16;"
        :: "r"(smem_dst), "l"(gsrc) : "memory");
}
__device__ __forceinline__ void cp_async_commit() {
    asm volatile("cp.async.commit_group;" ::: "memory");
}
__device__ __forceinline__ void cp_async_wait0() {
    asm volatile("cp.async.wait_group 0;" ::: "memory");
}

// set half #idx inside packed uint array (idx must be compile-time under unroll)
#define SET_HALF(arr, idx, f) do {                                        \
    uint32_t hv = (uint32_t)__half_as_ushort(__float2half(f));            \
    if ((idx) & 1) (arr)[(idx) >> 1] |= (hv << 16);                       \
    else           (arr)[(idx) >> 1] |= hv;                               \
} while (0)

// =====================================================================
// Feature-of-k permutation (matches stage_tile's staged A layout)
// =====================================================================
__device__ __forceinline__ int feat_of_k(int k) {
    if (k < 576) return 4 + k;
    int col = k - 576;
    if (col < 54)  return 580 + col;
    if (col < 56)  return -1;
    if (col < 110) return 634 + (col - 56);
    if (col < 114) return col - 110;
    return -1;
}

// =====================================================================
// Kernel 1 (merged): blocks [0, nbF): node features; blocks [nbF, nbF+11): bprep
// =====================================================================
__global__ void node_feat_bprep_kernel(const float* __restrict__ coords,
                                       const float* __restrict__ cX,
                                       const int*   __restrict__ batch,
                                       const float* __restrict__ eW,
                                       int n_res, int nbF)
{
    if (blockIdx.x >= (unsigned)nbF) {
        // ---- bprep: one chunk per block ----
        int c = blockIdx.x - nbF;
        char* img = (char*)(g_Bimg + (size_t)c * 16384);
        for (int i = threadIdx.x; i < 4096; i += blockDim.x) {
            int n = i >> 5, kp = i & 31;
            int k0 = c * 64 + kp * 2;
            int fa = feat_of_k(k0), fb = feat_of_k(k0 + 1);
            float w0 = (fa >= 0) ? eW[fa * HID + n] : 0.f;
            float w1 = (fb >= 0) ? eW[fb * HID + n] : 0.f;
            *(uint32_t*)(img + swz((uint32_t)(n * 128 + kp * 4))) = packh2(w0, w1);
        }
        return;
    }

    int r = blockIdx.x * blockDim.x + threadIdx.x;
    if (r >= n_res) return;
    const int L = n_res * N_ATOMS;

    bool bnd  = (r > 0)         && (batch[r]     != batch[r - 1]);
    bool bndn = (r < n_res - 1) && (batch[r + 1] != batch[r]);

    float xp[9][3];
    #pragma unroll
    for (int i = 0; i < 9; i++) {
        int j = 6 * r + i - 1;
        j = max(0, min(L - 1, j));
        xp[i][0] = coords[j * 3 + 0];
        xp[i][1] = coords[j * 3 + 1];
        xp[i][2] = coords[j * 3 + 2];
    }
    float U[8][3];
    #pragma unroll
    for (int i = 0; i < 8; i++) {
        float dx = xp[i + 1][0] - xp[i][0];
        float dy = xp[i + 1][1] - xp[i][1];
        float dz = xp[i + 1][2] - xp[i][2];
        norm3(dx, dy, dz);
        U[i][0] = dx; U[i][1] = dy; U[i][2] = dz;
    }

    float feat[44];
    #pragma unroll
    for (int a = 0; a < 6; a++) {
        int j = 6 * r + a;
        bool dm = (j >= 1) && (j <= L - 3) && !(bnd && a == 0) && !(bndn && a >= 4);
        float sv = 0.f, cv = 0.f;
        if (dm) {
            float c1x = U[a][1] * U[a + 1][2] - U[a][2] * U[a + 1][1];
            float c1y = U[a][2] * U[a + 1][0] - U[a][0] * U[a + 1][2];
            float c1z = U[a][0] * U[a + 1][1] - U[a][1] * U[a + 1][0];
            norm3(c1x, c1y, c1z);
            float c2x = U[a + 1][1] * U[a + 2][2] - U[a + 1][2] * U[a + 2][1];
            float c2y = U[a + 1][2] * U[a + 2][0] - U[a + 1][0] * U[a + 2][2];
            float c2z = U[a + 1][0] * U[a + 2][1] - U[a + 1][1] * U[a + 2][0];
            norm3(c2x, c2y, c2z);
            float d = c1x * c2x + c1y * c2y + c1z * c2z;
            d = fminf(fmaxf(d, -1.f + 1e-6f), 1.f - 1e-6f);
            float sg = sgnf(c2x * U[a][0] + c2y * U[a][1] + c2z * U[a][2]);
            float dih = acosf(d) * sg;
            sv = sinf(dih); cv = cosf(dih);
        }
        feat[2 * a]     = sv;
        feat[2 * a + 1] = cv;
        bool am = (j >= 1) && (j <= L - 2) && !(bnd && a == 0) && !(bndn && a == 5);
        float sa = 0.f, ca = 0.f;
        if (am) {
            float ax = xp[a][0] - xp[a + 1][0];
            float ay = xp[a][1] - xp[a + 1][1];
            float az = xp[a][2] - xp[a + 1][2];
            norm3(ax, ay, az);
            float bx = xp[a + 2][0] - xp[a + 1][0];
            float by = xp[a + 2][1] - xp[a + 1][1];
            float bz = xp[a + 2][2] - xp[a + 1][2];
            norm3(bx, by, bz);
            ca = ax * bx + ay * by + az * bz;
            sa = sqrtf(1.f - ca * ca + 1e-6f);
        }
        feat[12 + 2 * a] = sa;
        feat[13 + 2 * a] = ca;
    }

    float Q[3][3] = {{0.f,0.f,0.f},{0.f,0.f,0.f},{0.f,0.f,0.f}};
    bool qv = false;
    float cx0[3] = { cX[r * 3 + 0], cX[r * 3 + 1], cX[r * 3 + 2] };
    if (r >= 1 && r <= n_res - 2) {
        float cm[3] = { cX[(r - 1) * 3 + 0], cX[(r - 1) * 3 + 1], cX[(r - 1) * 3 + 2] };
        float cp[3] = { cX[(r + 1) * 3 + 0], cX[(r + 1) * 3 + 1], cX[(r + 1) * 3 + 2] };
        float u0x = cx0[0] - cm[0], u0y = cx0[1] - cm[1], u0z = cx0[2] - cm[2];
        norm3(u0x, u0y, u0z);
        float u1x = cp[0] - cx0[0], u1y = cp[1] - cx0[1], u1z = cp[2] - cx0[2];
        norm3(u1x, u1y, u1z);
        float bx = u0x - u1x, by = u0y - u1y, bz = u0z - u1z;
        norm3(bx, by, bz);
        float nx = u0y * u1z - u0z * u1y;
        float ny = u0z * u1x - u0x * u1z;
        float nz = u0x * u1y - u0y * u1x;
        norm3(nx, ny, nz);
        float ccx = by * nz - bz * ny;
        float ccy = bz * nx - bx * nz;
        float ccz = bx * ny - by * nx;
        qv = !bnd && !bndn;
        float m = qv ? 1.f : 0.f;
        Q[0][0] = bx * m; Q[0][1] = nx * m; Q[0][2] = ccx * m;
        Q[1][0] = by * m; Q[1][1] = ny * m; Q[1][2] = ccy * m;
        Q[2][0] = bz * m; Q[2][1] = nz * m; Q[2][2] = ccz * m;
    }
    g_valid[r] = qv ? 1 : 0;
    #pragma unroll
    for (int k = 0; k < 3; k++)
        #pragma unroll
        for (int j = 0; j < 3; j++)
            g_Q[r * 9 + k * 3 + j] = Q[k][j];

    const int keep[5] = {0, 2, 3, 4, 5};
    #pragma unroll
    for (int ai = 0; ai < 5; ai++) {
        int a = keep[ai];
        float dx = xp[a + 1][0] - cx0[0];
        float dy = xp[a + 1][1] - cx0[1];
        float dz = xp[a + 1][2] - cx0[2];
        float ss = dx * dx + dy * dy + dz * dz;
        feat[24 + ai] = 0.5f * logf(ss + 1e-6f);
        float inv = 1.f / fmaxf(sqrtf(ss), 1e-12f);
        float nx = dx * inv, ny = dy * inv, nz = dz * inv;
        #pragma unroll
        for (int i = 0; i < 3; i++)
            feat[29 + ai * 3 + i] = Q[0][i] * nx + Q[1][i] * ny + Q[2][i] * nz;
    }
    #pragma unroll
    for (int k = 0; k < 44; k++)
        g_nodeFeat[r * 44 + k] = feat[k];
}

// =====================================================================
// Kernel 2 (FUSED edge + node-gemm): blocks [0,tiles) do the edge tile;
// blocks [tiles, ...) do warp-per-residue node matvec + layernorm.
// Edge: M=128/CTA, N=128, K=704 in 11 chunks, order [9,10,0..8];
// chunks 9/10 staged directly into the A double-buffer. 2 CTAs/SM.
// smem: A[2]@0,16384 | B[2]@32768,49152 | D(36 planes f32)@65536 |
//       red(2KB)@83968.   total 86016 B
// =====================================================================
#define SB_OFF   32768
#define SD_OFF   65536
#define RED_OFF  83968
#define SMEM_TOT 86016

__device__ __forceinline__ void produce_B_async(uint32_t sb, int b, int c, int tid)
{
    const char* src = (const char*)(g_Bimg + (size_t)c * 16384);
    uint32_t dst = sb + SB_OFF + b * 16384;
    #pragma unroll
    for (int i = 0; i < 4; i++)
        cp_async16(dst + (tid + i * 256) * 16, src + (tid + i * 256) * 16);
    cp_async_commit();
}

__device__ __forceinline__ void stage_tile(char* smem,
                                           const float* __restrict__ coords,
                                           const int*   __restrict__ eidx,
                                           int n_edges, int e0, int tid)
{
    float* s_D = (float*)(smem + SD_OFF);
    int e = tid >> 1, half = tid & 1;
    int ge = min(e0 + e, n_edges - 1);
    int s = eidx[ge], t = eidx[n_edges + ge];

    float Qt[9];
    #pragma unroll
    for (int i = 0; i < 9; i++) Qt[i] = g_Q[t * 9 + i];
    float ct[9];
    #pragma unroll
    for (int j = 0; j < 9; j++) ct[j] = coords[t * 18 + half * 9 + j];
    float cs[18];
    #pragma unroll
    for (int j = 0; j < 18; j++) cs[j] = coords[s * 18 + j];

    uint32_t hb[32];
    #pragma unroll
    for (int j = 0; j < 32; j++) hb[j] = 0;

    #pragma unroll
    for (int pp = 0; pp < 18; pp++) {
        int tl = pp / 6, sa = pp % 6;
        int p  = half * 18 + pp;
        float dx = cs[sa * 3 + 0] - ct[tl * 3 + 0];
        float dy = cs[sa * 3 + 1] - ct[tl * 3 + 1];
        float dz = cs[sa * 3 + 2] - ct[tl * 3 + 2];
        float ss2 = dx * dx + dy * dy + dz * dz;
        s_D[p * 128 + e] = sqrtf(ss2 + 1e-6f);
        float inv = 1.f / fmaxf(sqrtf(ss2), 1e-12f);
        float nx = dx * inv, ny = dy * inv, nz = dz * inv;
        float v0 = Qt[0] * nx + Qt[3] * ny + Qt[6] * nz;
        float v1 = Qt[1] * nx + Qt[4] * ny + Qt[7] * nz;
        float v2 = Qt[2] * nx + Qt[5] * ny + Qt[8] * nz;
        SET_HALF(hb, pp * 3 + 0, v0);
        SET_HALF(hb, pp * 3 + 1, v1);
        SET_HALF(hb, pp * 3 + 2, v2);
    }

    if (half) {
        float Qs[9];
        #pragma unroll
        for (int i = 0; i < 9; i++) Qs[i] = g_Q[s * 9 + i];
        float m = (g_valid[s] && g_valid[t]) ? 1.f : 0.f;
        float R[3][3];
        #pragma unroll
        for (int i = 0; i < 3; i++)
            #pragma unroll
            for (int j = 0; j < 3; j++)
                R[i][j] = Qt[0 * 3 + i] * Qs[0 * 3 + j]
                        + Qt[1 * 3 + i] * Qs[1 * 3 + j]
                        + Qt[2 * 3 + i] * Qs[2 * 3 + j];
        float Rxx = R[0][0], Ryy = R[1][1], Rzz = R[2][2];
        float mx = 0.5f * sqrtf(fabsf(1.f + Rxx - Ryy - Rzz));
        float my = 0.5f * sqrtf(fabsf(1.f - Rxx + Ryy - Rzz));
        float mz = 0.5f * sqrtf(fabsf(1.f - Rxx - Ryy + Rzz));
        float x = sgnf(R[2][1] - R[1][2]) * mx;
        float y = sgnf(R[0][2] - R[2][0]) * my;
        float z = sgnf(R[1][0] - R[0][1]) * mz;
        float w = sqrtf(fmaxf(0.f, 1.f + Rxx + Ryy + Rzz)) * 0.5f;
        float nrm = sqrtf(x * x + y * y + z * z + w * w);
        float inv = 1.f / fmaxf(nrm, 1e-12f);
        SET_HALF(hb, 54, x * inv * m);
        SET_HALF(hb, 55, y * inv * m);
        SET_HALF(hb, 56, z * inv * m);
        SET_HALF(hb, 57, w * inv * m);
    }

    char* slot0 = smem;
    char* slot1 = smem + 16384;
    uint32_t base_col = half ? 56u : 0u;
    int ng = half ? 8 : 7;
    #pragma unroll
    for (int g = 0; g < 8; g++) {
        if (g < ng) {
            uint32_t colg = base_col + g * 8;
            char* sp = (colg < 64) ? slot0 : slot1;
            uint32_t cin = colg & 63;
            uint4 val = make_uint4(hb[g * 4], hb[g * 4 + 1], hb[g * 4 + 2], hb[g * 4 + 3]);
            *(uint4*)(sp + swz((uint32_t)(e * 128 + cin * 2))) = val;
        }
    }
    if (!half) {
        *(uint4*)(slot1 + swz((uint32_t)(e * 128 + 56 * 2))) = make_uint4(0, 0, 0, 0);
    }
}

// rbf chunks only (c = 0..8); stores as 2x uint4 (16B aligned swizzle units)
__device__ __forceinline__ void produce_A(char* smem, int b, int c, int tid)
{
    char* aBuf = smem + b * 16384;
    const float* s_D = (const float*)(smem + SD_OFF);
    const float DLc = 16.f / 15.f;
    const float DL2 = DLc * DLc;
    const float qc  = expf(-2.f * DL2);
    #pragma unroll
    for (int ii = 0; ii < 2; ii++) {
        int inst = tid + ii * 256;
        int pi = inst >> 7;
        int m  = inst & 127;
        float D  = s_D[(c * 4 + pi) * 128 + m];
        float t_ = 0.8f * D;
        float v  = expf(-t_ * t_);
        float r  = expf(2.f * DLc * t_ - DL2);
        uint32_t rowoff = (uint32_t)(m * 128 + pi * 32);
        uint4 u0, u1;
        {
            float v0 = v; v *= r; r *= qc;
            float v1 = v; v *= r; r *= qc;
            float v2 = v; v *= r; r *= qc;
            float v3 = v; v *= r; r *= qc;
            u0.x = packh2(v0, v1); u0.y = packh2(v2, v3);
            v0 = v; v *= r; r *= qc;
            v1 = v; v *= r; r *= qc;
            v2 = v; v *= r; r *= qc;
            v3 = v; v *= r; r *= qc;
            u0.z = packh2(v0, v1); u0.w = packh2(v2, v3);
            v0 = v; v *= r; r *= qc;
            v1 = v; v *= r; r *= qc;
            v2 = v; v *= r; r *= qc;
            v3 = v; v *= r; r *= qc;
            u1.x = packh2(v0, v1); u1.y = packh2(v2, v3);
            v0 = v; v *= r; r *= qc;
            v1 = v; v *= r; r *= qc;
            v2 = v; v *= r; r *= qc;
            v3 = v; v *= r; r *= qc;
            u1.z = packh2(v0, v1); u1.w = packh2(v2, v3);
        }
        *(uint4*)(aBuf + swz(rowoff))      = u0;
        *(uint4*)(aBuf + swz(rowoff + 16)) = u1;
    }
}

__device__ __forceinline__ void consume_chunk(uint32_t aBase, uint32_t bBase,
                                              float acc[2][8][4],
                                              int m_base, int n_base, int lane)
{
    int g     = lane >> 3;
    int arow  = (g & 1) * 8 + (lane & 7);
    int akoff = (g >> 1) * 8;
    int brow  = (g >> 1) * 8 + (lane & 7);
    int bkoff = (g & 1) * 8;
    #pragma unroll
    for (int k16 = 0; k16 < 4; k16++) {
        uint32_t aF[2][4];
        #pragma unroll
        for (int mblk = 0; mblk < 2; mblk++) {
            uint32_t off = swz((uint32_t)((m_base + mblk * 16 + arow) * 128
                                          + (k16 * 16 + akoff) * 2));
            ldm_x4(aF[mblk], aBase + off);
        }
        #pragma unroll
        for (int np = 0; np < 4; np++) {
            uint32_t bF[4];
            uint32_t off = swz((uint32_t)((n_base + np * 16 + brow) * 128
                                          + (k16 * 16 + bkoff) * 2));
            ldm_x4(bF, bBase + off);
            #pragma unroll
            for (int mblk = 0; mblk < 2; mblk++)
                #pragma unroll
                for (int ns = 0; ns < 2; ns++)
                    mma_fp16(acc[mblk][np * 2 + ns], aF[mblk], bF + ns * 2);
        }
    }
}

__global__ void __launch_bounds__(256, 2)
edge_fused_kernel(const float* __restrict__ coords,
                  const int*   __restrict__ eidx,
                  const float* __restrict__ bias,
                  const float* __restrict__ lnw,
                  const float* __restrict__ lnb,
                  const float* __restrict__ nW,
                  const float* __restrict__ nb,
                  const float* __restrict__ nlw,
                  const float* __restrict__ nlb,
                  float* __restrict__ out_node,
                  float* __restrict__ out_edge,
                  int n_edges, int n_res, int tiles)
{
    extern __shared__ char smem[];
    const int tid = threadIdx.x;
    const int w    = tid >> 5;
    const int lane = tid & 31;

    if (blockIdx.x >= (unsigned)tiles) {
        // ---- node matvec + layernorm: 8 residues per block, warp each ----
        int gw = (blockIdx.x - tiles) * 8 + w;
        if (gw >= n_res) return;
        const float* f = g_nodeFeat + gw * 44;
        float acc[4];
        #pragma unroll
        for (int u = 0; u < 4; u++) acc[u] = nb[lane + 32 * u];
        #pragma unroll 4
        for (int k = 0; k < 44; k++) {
            float fv = f[k];
            #pragma unroll
            for (int u = 0; u < 4; u++)
                acc[u] += fv * nW[k * HID + lane + 32 * u];
        }
        float s1 = acc[0] + acc[1] + acc[2] + acc[3];
        float s2 = acc[0]*acc[0] + acc[1]*acc[1] + acc[2]*acc[2] + acc[3]*acc[3];
        #pragma unroll
        for (int o = 16; o > 0; o >>= 1) {
            s1 += __shfl_xor_sync(0xffffffffu, s1, o);
            s2 += __shfl_xor_sync(0xffffffffu, s2, o);
        }
        float mu  = s1 * (1.f / 128.f);
        float var = s2 * (1.f / 128.f) - mu * mu;
        float rs  = rsqrtf(var + 1e-5f);
        #pragma unroll
        for (int u = 0; u < 4; u++) {
            int c = lane + 32 * u;
            out_node[(size_t)gw * HID + c] = (acc[u] - mu) * rs * nlw[c] + nlb[c];
        }
        return;
    }

    // ---- edge tile ----
    const uint32_t sb = smem_to_u32(smem);
    const int e0  = blockIdx.x * 128;
    float2* s_red = (float2*)(smem + RED_OFF);

    const int m_base = (w & 3) * 32;
    const int nh     = w >> 2;
    const int n_base = nh * 64;

    produce_B_async(sb, 0, 9, tid);
    stage_tile(smem, coords, eidx, n_edges, e0, tid);

    float acc[2][8][4];
    #pragma unroll
    for (int i = 0; i < 2; i++)
        #pragma unroll
        for (int j = 0; j < 8; j++)
            #pragma unroll
            for (int k = 0; k < 4; k++) acc[i][j][k] = 0.f;

    cp_async_wait0();
    __syncthreads();
    #pragma unroll 1
    for (int i = 0; i < 11; i++) {
        int slot = i & 1;
        if (i + 1 < 11) {
            int nc = (i == 0) ? 10 : (i - 1);
            produce_B_async(sb, (i + 1) & 1, nc, tid);
        }
        consume_chunk(sb + slot * 16384, sb + SB_OFF + slot * 16384,
                      acc, m_base, n_base, lane);
        if (i + 1 < 11) {
            if (i >= 1) produce_A(smem, (i + 1) & 1, i - 1, tid);
            cp_async_wait0();
        }
        __syncthreads();
    }

    // ---- epilogue: bias + layernorm ----
    const int qr = lane >> 2, qc2 = lane & 3;
    float s1[2][2] = {{0.f,0.f},{0.f,0.f}}, s2[2][2] = {{0.f,0.f},{0.f,0.f}};
    #pragma unroll
    for (int mblk = 0; mblk < 2; mblk++)
        #pragma unroll
        for (int nb2 = 0; nb2 < 8; nb2++) {
            int col = n_base + nb2 * 8 + qc2 * 2;
            float b0 = bias[col], b1 = bias[col + 1];
            #pragma unroll
            for (int rh = 0; rh < 2; rh++) {
                float v0 = acc[mblk][nb2][rh * 2]     + b0;
                float v1 = acc[mblk][nb2][rh * 2 + 1] + b1;
                acc[mblk][nb2][rh * 2]     = v0;
                acc[mblk][nb2][rh * 2 + 1] = v1;
                s1[mblk][rh] += v0 + v1;
                s2[mblk][rh] += v0 * v0 + v1 * v1;
            }
        }
    #pragma unroll
    for (int mblk = 0; mblk < 2; mblk++)
        #pragma unroll
        for (int rh = 0; rh < 2; rh++) {
            #pragma unroll
            for (int o = 1; o < 4; o <<= 1) {
                s1[mblk][rh] += __shfl_xor_sync(0xffffffffu, s1[mblk][rh], o);
                s2[mblk][rh] += __shfl_xor_sync(0xffffffffu, s2[mblk][rh], o);
            }
        }
    if (qc2 == 0) {
        #pragma unroll
        for (int mblk = 0; mblk < 2; mblk++)
            #pragma unroll
            for (int rh = 0; rh < 2; rh++) {
                int row = m_base + mblk * 16 + qr + rh * 8;
                s_red[row * 2 + nh] = make_float2(s1[mblk][rh], s2[mblk][rh]);
            }
    }
    __syncthreads();
    #pragma unroll
    for (int mblk = 0; mblk < 2; mblk++)
        #pragma unroll
        for (int rh = 0; rh < 2; rh++) {
            int row = m_base + mblk * 16 + qr + rh * 8;
            float2 r0 = s_red[row * 2], r1 = s_red[row * 2 + 1];
            float S1 = r0.x + r1.x, S2 = r0.y + r1.y;
            float mu  = S1 * (1.f / 128.f);
            float var = S2 * (1.f / 128.f) - mu * mu;
            float rs  = rsqrtf(var + 1e-5f);
            int ge = e0 + row;
            if (ge < n_edges) {
                #pragma unroll
                for (int nb2 = 0; nb2 < 8; nb2++) {
                    int col = n_base + nb2 * 8 + qc2 * 2;
                    float2 o;
                    o.x = (acc[mblk][nb2][rh * 2]     - mu) * rs * lnw[col]     + lnb[col];
                    o.y = (acc[mblk][nb2][rh * 2 + 1] - mu) * rs * lnw[col + 1] + lnb[col + 1];
                    *(float2*)(out_edge + (size_t)ge * HID + col) = o;
                }
            }
        }
}

// =====================================================================
extern "C" void kernel_launch(void* const* d_in, const int* in_sizes, int n_in,
                              void* d_out, int out_size)
{
    const float* coords = (const float*)d_in[0];
    const float* cX     = (const float*)d_in[1];
    const float* nW     = (const float*)d_in[2];
    const float* nb     = (const float*)d_in[3];
    const float* nlw    = (const float*)d_in[4];
    const float* nlb    = (const float*)d_in[5];
    const float* eW     = (const float*)d_in[6];
    const float* ebias  = (const float*)d_in[7];
    const float* elw    = (const float*)d_in[8];
    const float* elb    = (const float*)d_in[9];
    const int*   batch  = (const int*)d_in[10];
    const int*   eidx   = (const int*)d_in[11];

    int n_res   = in_sizes[0] / (N_ATOMS * 3);
    int n_edges = in_sizes[11] / 2;
    int tiles   = (n_edges + 127) / 128;
    int nbF     = (n_res + 127) / 128;
    int nodeBlocks = (n_res + 7) / 8;
    float* out  = (float*)d_out;

    cudaFuncSetAttribute(edge_fused_kernel,
                         cudaFuncAttributeMaxDynamicSharedMemorySize, SMEM_TOT);

    node_feat_bprep_kernel<<<nbF + N_CHUNKS, 128>>>(coords, cX, batch, eW, n_res, nbF);
    edge_fused_kernel<<<tiles + nodeBlocks, 256, SMEM_TOT>>>(
        coords, eidx, ebias, elw, elb, nW, nb, nlw, nlb,
        out, out + (size_t)n_res * HID, n_edges, n_res, tiles);
}